// round 17
// baseline (speedup 1.0000x reference)
#include <cuda_runtime.h>
#include <cuda_bf16.h>
#include <math.h>
#include <cstdint>

#define Bb 2
#define Nn 160
#define Cc 256
#define Hh 8
#define Dd 32
#define ROWS (Bb*Nn*Nn)   // 51200
#define GK 256            // inner K of all GEMMs

typedef unsigned long long ull;

// ---------------- scratch (__device__ globals; no allocation allowed) ----------------
__device__ __nv_bfloat16 g_qkvh[(size_t)ROWS*768];
__device__ __nv_bfloat16 g_qkvl[(size_t)ROWS*768];
__device__ float g_x1[(size_t)ROWS*Cc];
__device__ float g_mapT[(size_t)Bb*Nn*Nn];
__device__ __nv_bfloat16 g_Ah[(size_t)ROWS*GK];
__device__ __nv_bfloat16 g_Al[(size_t)ROWS*GK];
__device__ __nv_bfloat16 g_Xh[(size_t)ROWS*GK];
__device__ __nv_bfloat16 g_Xl[(size_t)ROWS*GK];
__device__ __nv_bfloat16 g_Brq[(size_t)768*2*GK];
__device__ __nv_bfloat16 g_Bro[(size_t)256*2*GK];
__device__ __nv_bfloat16 g_Bcq[(size_t)768*2*GK];
__device__ __nv_bfloat16 g_Bco[(size_t)256*2*GK];

__device__ __forceinline__ uint32_t smem_u32(const void* p) {
    uint32_t a;
    asm("{ .reg .u64 t; cvta.to.shared.u64 t, %1; cvt.u32.u64 %0, t; }" : "=r"(a) : "l"(p));
    return a;
}
#define CP16(d, s) asm volatile("cp.async.cg.shared.global [%0], [%1], 16;" :: "r"(d), "l"(s))
#define CP_COMMIT  asm volatile("cp.async.commit_group;" ::: "memory")

__device__ __forceinline__ uint32_t bpack(__nv_bfloat16 a, __nv_bfloat16 b) {
    __nv_bfloat162 t(a, b);
    return *reinterpret_cast<uint32_t*>(&t);
}
__device__ __forceinline__ void split2(float x, float y, uint32_t& hi, uint32_t& lo) {
    __nv_bfloat16 hx = __float2bfloat16(x), hy = __float2bfloat16(y);
    hi = bpack(hx, hy);
    lo = bpack(__float2bfloat16(x - __bfloat162float(hx)),
               __float2bfloat16(y - __bfloat162float(hy)));
}

#define MMA16816(d, a, b) \
    asm volatile("mma.sync.aligned.m16n8k16.row.col.f32.bf16.bf16.f32 " \
                 "{%0,%1,%2,%3}, {%4,%5,%6,%7}, {%8,%9}, {%0,%1,%2,%3};" \
                 : "+f"((d)[0]), "+f"((d)[1]), "+f"((d)[2]), "+f"((d)[3]) \
                 : "r"((a)[0]), "r"((a)[1]), "r"((a)[2]), "r"((a)[3]), \
                   "r"((b)[0]), "r"((b)[1]))

#define LDSM_X4(r, addr) \
    asm volatile("ldmatrix.sync.aligned.m8n8.x4.shared.b16 {%0,%1,%2,%3}, [%4];" \
                 : "=r"((r)[0]), "=r"((r)[1]), "=r"((r)[2]), "=r"((r)[3]) : "r"(addr))
#define LDSM_X2(r0, r1, addr) \
    asm volatile("ldmatrix.sync.aligned.m8n8.x2.shared.b16 {%0,%1}, [%2];" \
                 : "=r"(r0), "=r"(r1) : "r"(addr))
#define LDSM_X4T(r, addr) \
    asm volatile("ldmatrix.sync.aligned.m8n8.x4.trans.shared.b16 {%0,%1,%2,%3}, [%4];" \
                 : "=r"((r)[0]), "=r"((r)[1]), "=r"((r)[2]), "=r"((r)[3]) : "r"(addr))

// ---------------- map transpose: mapT[b,i,j] = map[b,j,i] ----------------
__global__ __launch_bounds__(256) void tmap_kernel(const float* __restrict__ m,
                                                   float* __restrict__ mt) {
    __shared__ float tile[32][33];
    const int b = blockIdx.z;
    const int x = blockIdx.x * 32 + threadIdx.x;
    const int ty = threadIdx.y;
#pragma unroll
    for (int dy = 0; dy < 32; dy += 8) {
        int y = blockIdx.y * 32 + ty + dy;
        tile[ty + dy][threadIdx.x] = m[(size_t)b * Nn * Nn + (size_t)y * Nn + x];
    }
    __syncthreads();
    const int xo = blockIdx.y * 32 + threadIdx.x;
#pragma unroll
    for (int dy = 0; dy < 32; dy += 8) {
        int yo = blockIdx.x * 32 + ty + dy;
        mt[(size_t)b * Nn * Nn + (size_t)yo * Nn + xo] = tile[threadIdx.x][ty + dy];
    }
}

// ---------------- fused weight split ----------------
__device__ __forceinline__ void wsplit_one(const float* W, __nv_bfloat16* Bt, int Nc, int idx) {
    int k = idx / Nc, n = idx % Nc;
    float x = W[idx];
    __nv_bfloat16 h = __float2bfloat16(x);
    Bt[(size_t)n * (2 * GK) + k]      = h;
    Bt[(size_t)n * (2 * GK) + GK + k] = __float2bfloat16(x - __bfloat162float(h));
}
__global__ __launch_bounds__(256) void splitW(const float* __restrict__ wrq,
                                              const float* __restrict__ wro,
                                              const float* __restrict__ wcq,
                                              const float* __restrict__ wco,
                                              __nv_bfloat16* __restrict__ brq,
                                              __nv_bfloat16* __restrict__ bro,
                                              __nv_bfloat16* __restrict__ bcq,
                                              __nv_bfloat16* __restrict__ bco) {
    int idx = blockIdx.x * blockDim.x + threadIdx.x;
    const int NQ = GK * 768, NO = GK * 256;
    if (idx < NQ) { wsplit_one(wrq, brq, 768, idx); return; }
    idx -= NQ;
    if (idx < NQ) { wsplit_one(wcq, bcq, 768, idx); return; }
    idx -= NQ;
    if (idx < NO) { wsplit_one(wro, bro, 256, idx); return; }
    idx -= NO;
    if (idx < NO) { wsplit_one(wco, bco, 256, idx); }
}

// ---------------- splitA: fp32 -> bf16 hi/lo ----------------
__global__ __launch_bounds__(256) void splitA(const float4* __restrict__ X,
                                              __nv_bfloat16* __restrict__ Ah,
                                              __nv_bfloat16* __restrict__ Al, int n4) {
    int i = blockIdx.x * blockDim.x + threadIdx.x;
    if (i >= n4) return;
    float4 x = X[i];
    uint32_t h0, l0, h1, l1;
    split2(x.x, x.y, h0, l0);
    split2(x.z, x.w, h1, l1);
    reinterpret_cast<uint32_t*>(Ah)[i * 2 + 0] = h0;
    reinterpret_cast<uint32_t*>(Ah)[i * 2 + 1] = h1;
    reinterpret_cast<uint32_t*>(Al)[i * 2 + 0] = l0;
    reinterpret_cast<uint32_t*>(Al)[i * 2 + 1] = l1;
}

// ---------------- bf16 mma.sync GEMM, BM=128 BN=128 (qkv; writes bf16 hi/lo) ----------------
#define SSTR 40
#define GTILE (128 * SSTR)
#define NCHUNK (GK / 32)
#define GSMEM (2 * 4 * GTILE * 2)

__global__ __launch_bounds__(256, 2) void gemm_mma(const __nv_bfloat16* __restrict__ Ah,
                                                const __nv_bfloat16* __restrict__ Al,
                                                const __nv_bfloat16* __restrict__ Bt,
                                                __nv_bfloat16* __restrict__ Ch,
                                                __nv_bfloat16* __restrict__ Cl, int Nc) {
    extern __shared__ __nv_bfloat16 gsm[];

    const int tid = threadIdx.x;
    const int wid = tid >> 5, l = tid & 31;
    const int wm = (wid & 3) * 32;
    const int wn = (wid >> 2) * 64;
    const int bm = blockIdx.y * 128, bn = blockIdx.x * 128;

    float acc[2][8][4];
#pragma unroll
    for (int mt = 0; mt < 2; mt++)
#pragma unroll
        for (int nt = 0; nt < 8; nt++)
#pragma unroll
            for (int r = 0; r < 4; r++) acc[mt][nt][r] = 0.f;

    auto load_chunk = [&](int c, int st) {
        const int k0 = c * 32;
        __nv_bfloat16* base = gsm + st * 4 * GTILE;
#pragma unroll
        for (int w = 0; w < 2; w++) {
            int idx = tid + w * 256;
            int row = idx >> 2, seg = (idx & 3) * 8;
            uint32_t soff = (uint32_t)(row * SSTR + seg);
            CP16(smem_u32(base + 0 * GTILE + soff),
                 Ah + (size_t)(bm + row) * GK + k0 + seg);
            CP16(smem_u32(base + 1 * GTILE + soff),
                 Al + (size_t)(bm + row) * GK + k0 + seg);
            CP16(smem_u32(base + 2 * GTILE + soff),
                 Bt + (size_t)(bn + row) * (2 * GK) + k0 + seg);
            CP16(smem_u32(base + 3 * GTILE + soff),
                 Bt + (size_t)(bn + row) * (2 * GK) + GK + k0 + seg);
        }
        CP_COMMIT;
    };

    load_chunk(0, 0);

    int st = 0;
    for (int c = 0; c < NCHUNK; c++) {
        asm volatile("cp.async.wait_group 0;" ::: "memory");
        __syncthreads();
        if (c + 1 < NCHUNK) load_chunk(c + 1, st ^ 1);

        const __nv_bfloat16* base = gsm + st * 4 * GTILE;
        const uint32_t aHb = smem_u32(base + 0 * GTILE);
        const uint32_t aLb = smem_u32(base + 1 * GTILE);
        const uint32_t bHb = smem_u32(base + 2 * GTILE);
        const uint32_t bLb = smem_u32(base + 3 * GTILE);

#pragma unroll
        for (int ks = 0; ks < 32; ks += 16) {
            uint32_t ah[2][4], al[2][4], bh[8][2], bl[8][2];
            uint32_t aoff[2], boff[4];
#pragma unroll
            for (int mt = 0; mt < 2; mt++)
                aoff[mt] = (((wm + mt * 16 + (l & 15)) * SSTR) + ks + ((l >> 4) << 3)) * 2;
#pragma unroll
            for (int p = 0; p < 4; p++)
                boff[p] = (((wn + p * 16 + (l & 7) + ((l >> 4) << 3)) * SSTR) +
                           ks + (((l >> 3) & 1) << 3)) * 2;

#pragma unroll
            for (int mt = 0; mt < 2; mt++) LDSM_X4(ah[mt], aHb + aoff[mt]);
#pragma unroll
            for (int p = 0; p < 4; p++)
                asm volatile("ldmatrix.sync.aligned.m8n8.x4.shared.b16 {%0,%1,%2,%3}, [%4];"
                             : "=r"(bh[p * 2][0]), "=r"(bh[p * 2][1]),
                               "=r"(bh[p * 2 + 1][0]), "=r"(bh[p * 2 + 1][1])
                             : "r"(bHb + boff[p]));
#pragma unroll
            for (int mt = 0; mt < 2; mt++)
#pragma unroll
                for (int nt = 0; nt < 8; nt++) MMA16816(acc[mt][nt], ah[mt], bh[nt]);

#pragma unroll
            for (int p = 0; p < 4; p++)
                asm volatile("ldmatrix.sync.aligned.m8n8.x4.shared.b16 {%0,%1,%2,%3}, [%4];"
                             : "=r"(bl[p * 2][0]), "=r"(bl[p * 2][1]),
                               "=r"(bl[p * 2 + 1][0]), "=r"(bl[p * 2 + 1][1])
                             : "r"(bLb + boff[p]));
#pragma unroll
            for (int mt = 0; mt < 2; mt++)
#pragma unroll
                for (int nt = 0; nt < 8; nt++) MMA16816(acc[mt][nt], ah[mt], bl[nt]);

#pragma unroll
            for (int mt = 0; mt < 2; mt++) LDSM_X4(al[mt], aLb + aoff[mt]);
#pragma unroll
            for (int mt = 0; mt < 2; mt++)
#pragma unroll
                for (int nt = 0; nt < 8; nt++) MMA16816(acc[mt][nt], al[mt], bh[nt]);
        }
        st ^= 1;
    }

#pragma unroll
    for (int mt = 0; mt < 2; mt++) {
        const int row = bm + wm + mt * 16 + (l >> 2);
#pragma unroll
        for (int nt = 0; nt < 8; nt++) {
            const int col = bn + wn + nt * 8 + (l & 3) * 2;
            uint32_t h0, l0, h1, l1;
            split2(acc[mt][nt][0], acc[mt][nt][1], h0, l0);
            split2(acc[mt][nt][2], acc[mt][nt][3], h1, l1);
            *reinterpret_cast<uint32_t*>(Ch + (size_t)row * Nc + col)       = h0;
            *reinterpret_cast<uint32_t*>(Cl + (size_t)row * Nc + col)       = l0;
            *reinterpret_cast<uint32_t*>(Ch + (size_t)(row + 8) * Nc + col) = h1;
            *reinterpret_cast<uint32_t*>(Cl + (size_t)(row + 8) * Nc + col) = l1;
        }
    }
}

// ---------------- fused proj GEMM + residual + LayerNorm (BM=64, BN=256=full row) ----------------
// out[rt, :] = LN(xin[R,:] + A[R,:] @ W)[...], rt = transpose(R); optional bf16 hi/lo emit.
#define LATILE (64 * SSTR)                        // 2560
#define LBTILE (256 * SSTR)                       // 10240
#define LSTAGE (2 * LATILE + 2 * LBTILE)          // 25600 bf16
#define LSMEM  (2 * LSTAGE * 2)                   // 102400 B

__global__ __launch_bounds__(256, 2) void gemm_ln(const __nv_bfloat16* __restrict__ Ah,
                                                  const __nv_bfloat16* __restrict__ Al,
                                                  const __nv_bfloat16* __restrict__ Bt,
                                                  const float* __restrict__ xin,
                                                  const float* __restrict__ g,
                                                  const float* __restrict__ bt,
                                                  float* __restrict__ out,
                                                  __nv_bfloat16* __restrict__ Oh,
                                                  __nv_bfloat16* __restrict__ Ol) {
    extern __shared__ __nv_bfloat16 gsm[];

    const int tid = threadIdx.x;
    const int wid = tid >> 5, l = tid & 31;
    const int wm = (wid & 1) * 32;
    const int wn = (wid >> 1) * 64;
    const int bm = blockIdx.x * 64;
    const int cpair = (l & 3) * 2;

    float acc[2][8][4];
#pragma unroll
    for (int mt = 0; mt < 2; mt++)
#pragma unroll
        for (int nt = 0; nt < 8; nt++)
#pragma unroll
            for (int r = 0; r < 4; r++) acc[mt][nt][r] = 0.f;

    auto load_chunk = [&](int c, int st) {
        const int k0 = c * 32;
        __nv_bfloat16* base = gsm + st * LSTAGE;
        {   // A: 64 rows x 4 segs, hi+lo
            int row = tid >> 2, seg = (tid & 3) * 8;
            uint32_t soff = (uint32_t)(row * SSTR + seg);
            CP16(smem_u32(base + soff),          Ah + (size_t)(bm + row) * GK + k0 + seg);
            CP16(smem_u32(base + LATILE + soff), Al + (size_t)(bm + row) * GK + k0 + seg);
        }
#pragma unroll
        for (int w = 0; w < 4; w++) {   // B: 256 rows x 4 segs, hi+lo
            int idx = tid + w * 256;
            int row = idx >> 2, seg = (idx & 3) * 8;
            uint32_t soff = (uint32_t)(row * SSTR + seg);
            CP16(smem_u32(base + 2 * LATILE + soff),
                 Bt + (size_t)row * (2 * GK) + k0 + seg);
            CP16(smem_u32(base + 2 * LATILE + LBTILE + soff),
                 Bt + (size_t)row * (2 * GK) + GK + k0 + seg);
        }
        CP_COMMIT;
    };

    load_chunk(0, 0);

    int st = 0;
    for (int c = 0; c < NCHUNK; c++) {
        asm volatile("cp.async.wait_group 0;" ::: "memory");
        __syncthreads();
        if (c + 1 < NCHUNK) load_chunk(c + 1, st ^ 1);

        const __nv_bfloat16* base = gsm + st * LSTAGE;
        const uint32_t aHb = smem_u32(base);
        const uint32_t aLb = smem_u32(base + LATILE);
        const uint32_t bHb = smem_u32(base + 2 * LATILE);
        const uint32_t bLb = smem_u32(base + 2 * LATILE + LBTILE);

#pragma unroll
        for (int ks = 0; ks < 32; ks += 16) {
            uint32_t ah[2][4], al[2][4], bh[8][2], bl[8][2];
            uint32_t aoff[2], boff[4];
#pragma unroll
            for (int mt = 0; mt < 2; mt++)
                aoff[mt] = (((wm + mt * 16 + (l & 15)) * SSTR) + ks + ((l >> 4) << 3)) * 2;
#pragma unroll
            for (int p = 0; p < 4; p++)
                boff[p] = (((wn + p * 16 + (l & 7) + ((l >> 4) << 3)) * SSTR) +
                           ks + (((l >> 3) & 1) << 3)) * 2;

#pragma unroll
            for (int mt = 0; mt < 2; mt++) LDSM_X4(ah[mt], aHb + aoff[mt]);
#pragma unroll
            for (int p = 0; p < 4; p++)
                asm volatile("ldmatrix.sync.aligned.m8n8.x4.shared.b16 {%0,%1,%2,%3}, [%4];"
                             : "=r"(bh[p * 2][0]), "=r"(bh[p * 2][1]),
                               "=r"(bh[p * 2 + 1][0]), "=r"(bh[p * 2 + 1][1])
                             : "r"(bHb + boff[p]));
#pragma unroll
            for (int mt = 0; mt < 2; mt++)
#pragma unroll
                for (int nt = 0; nt < 8; nt++) MMA16816(acc[mt][nt], ah[mt], bh[nt]);

#pragma unroll
            for (int p = 0; p < 4; p++)
                asm volatile("ldmatrix.sync.aligned.m8n8.x4.shared.b16 {%0,%1,%2,%3}, [%4];"
                             : "=r"(bl[p * 2][0]), "=r"(bl[p * 2][1]),
                               "=r"(bl[p * 2 + 1][0]), "=r"(bl[p * 2 + 1][1])
                             : "r"(bLb + boff[p]));
#pragma unroll
            for (int mt = 0; mt < 2; mt++)
#pragma unroll
                for (int nt = 0; nt < 8; nt++) MMA16816(acc[mt][nt], ah[mt], bl[nt]);

#pragma unroll
            for (int mt = 0; mt < 2; mt++) LDSM_X4(al[mt], aLb + aoff[mt]);
#pragma unroll
            for (int mt = 0; mt < 2; mt++)
#pragma unroll
                for (int nt = 0; nt < 8; nt++) MMA16816(acc[mt][nt], al[mt], bh[nt]);
        }
        st ^= 1;
    }

    // ---------------- fused epilogue: residual + LN + transposed write ----------------
    __syncthreads();                               // tiles dead; reuse smem for reduction
    float* red = reinterpret_cast<float*>(gsm);    // [64 rows][4 nwarps][2]

    float rsum[4], rsq[4];
#pragma unroll
    for (int q = 0; q < 4; q++) {
        const int mt = q >> 1, half = q & 1;
        const int row = wm + mt * 16 + half * 8 + (l >> 2);
        const float* xr = xin + (size_t)(bm + row) * Cc;
        float s = 0.f, s2 = 0.f;
#pragma unroll
        for (int nt = 0; nt < 8; nt++) {
            const int col = wn + nt * 8 + cpair;
            float2 xi = *reinterpret_cast<const float2*>(xr + col);
            float v0 = acc[mt][nt][half * 2 + 0] + xi.x;
            float v1 = acc[mt][nt][half * 2 + 1] + xi.y;
            acc[mt][nt][half * 2 + 0] = v0;
            acc[mt][nt][half * 2 + 1] = v1;
            s += v0 + v1;
            s2 += v0 * v0 + v1 * v1;
        }
        s  += __shfl_xor_sync(0xffffffffu, s, 1);
        s  += __shfl_xor_sync(0xffffffffu, s, 2);
        s2 += __shfl_xor_sync(0xffffffffu, s2, 1);
        s2 += __shfl_xor_sync(0xffffffffu, s2, 2);
        rsum[q] = s; rsq[q] = s2;
        if ((l & 3) == 0) {
            red[row * 8 + (wid >> 1) * 2 + 0] = s;
            red[row * 8 + (wid >> 1) * 2 + 1] = s2;
        }
    }
    __syncthreads();

#pragma unroll
    for (int q = 0; q < 4; q++) {
        const int mt = q >> 1, half = q & 1;
        const int row = wm + mt * 16 + half * 8 + (l >> 2);
        float S = 0.f, S2 = 0.f;
#pragma unroll
        for (int w = 0; w < 4; w++) {
            S  += red[row * 8 + w * 2 + 0];
            S2 += red[row * 8 + w * 2 + 1];
        }
        const float mean = S * (1.f / Cc);
        const float var  = S2 * (1.f / Cc) - mean * mean;
        const float rs   = rsqrtf(var + 1e-5f);

        const int R    = bm + row;
        const int bidx = R / (Nn * Nn);
        const int rem  = R % (Nn * Nn);
        const int mm   = rem / Nn;
        const int ii   = rem % Nn;
        const size_t rt = ((size_t)bidx * Nn + ii) * Nn + mm;
        float* orow = out + rt * Cc;

#pragma unroll
        for (int nt = 0; nt < 8; nt++) {
            const int col = wn + nt * 8 + cpair;
            float2 gg = *reinterpret_cast<const float2*>(g + col);
            float2 bb2 = *reinterpret_cast<const float2*>(bt + col);
            float y0 = (acc[mt][nt][half * 2 + 0] - mean) * rs * gg.x + bb2.x;
            float y1 = (acc[mt][nt][half * 2 + 1] - mean) * rs * gg.y + bb2.y;
            *reinterpret_cast<float2*>(orow + col) = make_float2(y0, y1);
            if (Oh) {
                uint32_t hv, lv;
                split2(y0, y1, hv, lv);
                *reinterpret_cast<uint32_t*>(Oh + rt * GK + col) = hv;
                *reinterpret_cast<uint32_t*>(Ol + rt * GK + col) = lv;
            }
        }
    }
}

// ---------------- tensor-core attention: 2 heads per block, Q hoisted pre-wait ----------------
#define ASTR 40
#define AT_TILE (Nn * ASTR)
#define MSTR 168
#define MAP_SM (Nn * MSTR)
#define ATTN_SMEM (MAP_SM * 4 + 2 * 4 * AT_TILE * 2)

__global__ __launch_bounds__(320, 1) void attn_mma(const __nv_bfloat16* __restrict__ qkvh,
                                                   const __nv_bfloat16* __restrict__ qkvl,
                                                   const float* __restrict__ mapsrc,
                                                   const float* __restrict__ bw,
                                                   const float* __restrict__ bb,
                                                   __nv_bfloat16* __restrict__ Ah,
                                                   __nv_bfloat16* __restrict__ Al) {
    extern __shared__ char asmem[];
    float* mapS = reinterpret_cast<float*>(asmem);
    __nv_bfloat16* tiles = reinterpret_cast<__nv_bfloat16*>(asmem + MAP_SM * 4);
    auto sKh = [&](int st) { return tiles + st * 4 * AT_TILE + 0 * AT_TILE; };
    auto sKl = [&](int st) { return tiles + st * 4 * AT_TILE + 1 * AT_TILE; };
    auto sVh = [&](int st) { return tiles + st * 4 * AT_TILE + 2 * AT_TILE; };
    auto sVl = [&](int st) { return tiles + st * 4 * AT_TILE + 3 * AT_TILE; };

    const int m = blockIdx.x, b = blockIdx.y;
    const int hbase = blockIdx.z * 2;
    const int tid = threadIdx.x, wid = tid >> 5, l = tid & 31;
    const size_t rowbase = ((size_t)b * Nn + m) * Nn;
    const float scale = 0.17677669529663687f;

    for (int idx = tid; idx < Nn * 40; idx += 320) {
        int row = idx / 40, c4 = idx % 40;
        CP16(smem_u32(mapS + row * MSTR + c4 * 4),
             mapsrc + (size_t)b * Nn * Nn + (size_t)row * Nn + c4 * 4);
    }
    CP_COMMIT;

    auto load_kv = [&](int h, int st) {
        for (int idx = tid; idx < Nn * 4; idx += 320) {
            int row = idx >> 2, seg = (idx & 3) * 8;
            size_t gro = (rowbase + row) * 768 + 256 + h * Dd;
            uint32_t so = (uint32_t)(row * ASTR + seg);
            CP16(smem_u32(sKh(st) + so), qkvh + gro + seg);
            CP16(smem_u32(sKl(st) + so), qkvl + gro + seg);
            CP16(smem_u32(sVh(st) + so), qkvh + gro + 256 + seg);
            CP16(smem_u32(sVl(st) + so), qkvl + gro + 256 + seg);
        }
        CP_COMMIT;
    };

    load_kv(hbase, 0);

    const int q0 = wid * 16;
    const int r0 = q0 + (l >> 2), r1 = r0 + 8;
    const int cpair = (l & 3) * 2;

    for (int e = 0; e < 2; e++) {
        const int h = hbase + e, st = e;

        uint32_t qh[2][4], ql[2][4];
        {
            const size_t g0 = (rowbase + r0) * 768 + h * Dd;
            const size_t g1 = (rowbase + r1) * 768 + h * Dd;
#pragma unroll
            for (int kc = 0; kc < 2; kc++) {
                int col = kc * 16 + cpair;
                qh[kc][0] = *reinterpret_cast<const uint32_t*>(qkvh + g0 + col);
                qh[kc][1] = *reinterpret_cast<const uint32_t*>(qkvh + g1 + col);
                qh[kc][2] = *reinterpret_cast<const uint32_t*>(qkvh + g0 + col + 8);
                qh[kc][3] = *reinterpret_cast<const uint32_t*>(qkvh + g1 + col + 8);
                ql[kc][0] = *reinterpret_cast<const uint32_t*>(qkvl + g0 + col);
                ql[kc][1] = *reinterpret_cast<const uint32_t*>(qkvl + g1 + col);
                ql[kc][2] = *reinterpret_cast<const uint32_t*>(qkvl + g0 + col + 8);
                ql[kc][3] = *reinterpret_cast<const uint32_t*>(qkvl + g1 + col + 8);
            }
        }

        if (e == 0) {
            load_kv(hbase + 1, 1);
            asm volatile("cp.async.wait_group 1;" ::: "memory");
        } else {
            asm volatile("cp.async.wait_group 0;" ::: "memory");
        }
        __syncthreads();

        const float wv = bw[h], bv = bb[h];

        float S[20][4];
#pragma unroll
        for (int nt = 0; nt < 20; nt++)
#pragma unroll
            for (int r = 0; r < 4; r++) S[nt][r] = 0.f;

        const uint32_t kHb = smem_u32(sKh(st)), kLb = smem_u32(sKl(st));
#pragma unroll
        for (int nt = 0; nt < 20; nt++) {
#pragma unroll
            for (int kc = 0; kc < 2; kc++) {
                uint32_t off = (uint32_t)((nt * 8 + (l & 7)) * ASTR) * 2 +
                               (((l >> 3) & 1) << 4) + kc * 32;
                uint32_t bh[2], bl2[2];
                LDSM_X2(bh[0], bh[1], kHb + off);
                LDSM_X2(bl2[0], bl2[1], kLb + off);
                MMA16816(S[nt], qh[kc], bh);
                MMA16816(S[nt], qh[kc], bl2);
                MMA16816(S[nt], ql[kc], bh);
            }
        }

#pragma unroll
        for (int nt = 0; nt < 20; nt++) {
            int j0 = nt * 8 + cpair;
            S[nt][0] = S[nt][0] * scale + mapS[r0 * MSTR + j0]     * wv + bv;
            S[nt][1] = S[nt][1] * scale + mapS[r0 * MSTR + j0 + 1] * wv + bv;
            S[nt][2] = S[nt][2] * scale + mapS[r1 * MSTR + j0]     * wv + bv;
            S[nt][3] = S[nt][3] * scale + mapS[r1 * MSTR + j0 + 1] * wv + bv;
        }

        float m0 = -INFINITY, m1 = -INFINITY;
#pragma unroll
        for (int nt = 0; nt < 20; nt++) {
            m0 = fmaxf(m0, fmaxf(S[nt][0], S[nt][1]));
            m1 = fmaxf(m1, fmaxf(S[nt][2], S[nt][3]));
        }
        m0 = fmaxf(m0, __shfl_xor_sync(0xffffffffu, m0, 1));
        m0 = fmaxf(m0, __shfl_xor_sync(0xffffffffu, m0, 2));
        m1 = fmaxf(m1, __shfl_xor_sync(0xffffffffu, m1, 1));
        m1 = fmaxf(m1, __shfl_xor_sync(0xffffffffu, m1, 2));

        float l0 = 0.f, l1 = 0.f;
#pragma unroll
        for (int nt = 0; nt < 20; nt++) {
            S[nt][0] = __expf(S[nt][0] - m0); l0 += S[nt][0];
            S[nt][1] = __expf(S[nt][1] - m0); l0 += S[nt][1];
            S[nt][2] = __expf(S[nt][2] - m1); l1 += S[nt][2];
            S[nt][3] = __expf(S[nt][3] - m1); l1 += S[nt][3];
        }
        l0 += __shfl_xor_sync(0xffffffffu, l0, 1);
        l0 += __shfl_xor_sync(0xffffffffu, l0, 2);
        l1 += __shfl_xor_sync(0xffffffffu, l1, 1);
        l1 += __shfl_xor_sync(0xffffffffu, l1, 2);

        float O[4][4];
#pragma unroll
        for (int nt = 0; nt < 4; nt++)
#pragma unroll
            for (int r = 0; r < 4; r++) O[nt][r] = 0.f;

        const uint32_t vHb = smem_u32(sVh(st)), vLb = smem_u32(sVl(st));
#pragma unroll
        for (int kc = 0; kc < 10; kc++) {
            uint32_t aPh[4], aPl[4];
            split2(S[kc * 2][0],     S[kc * 2][1],     aPh[0], aPl[0]);
            split2(S[kc * 2][2],     S[kc * 2][3],     aPh[1], aPl[1]);
            split2(S[kc * 2 + 1][0], S[kc * 2 + 1][1], aPh[2], aPl[2]);
            split2(S[kc * 2 + 1][2], S[kc * 2 + 1][3], aPh[3], aPl[3]);

            uint32_t bvh[4][2], bvl[4][2];
#pragma unroll
            for (int dp = 0; dp < 2; dp++) {
                uint32_t off = (uint32_t)((kc * 16 + (l & 15)) * ASTR) * 2 +
                               ((l >> 4) << 4) + dp * 32;
                uint32_t rh[4], rl[4];
                LDSM_X4T(rh, vHb + off);
                LDSM_X4T(rl, vLb + off);
                bvh[dp * 2][0] = rh[0]; bvh[dp * 2][1] = rh[1];
                bvh[dp * 2 + 1][0] = rh[2]; bvh[dp * 2 + 1][1] = rh[3];
                bvl[dp * 2][0] = rl[0]; bvl[dp * 2][1] = rl[1];
                bvl[dp * 2 + 1][0] = rl[2]; bvl[dp * 2 + 1][1] = rl[3];
            }
#pragma unroll
            for (int nt = 0; nt < 4; nt++) {
                MMA16816(O[nt], aPh, bvh[nt]);
                MMA16816(O[nt], aPh, bvl[nt]);
                MMA16816(O[nt], aPl, bvh[nt]);
            }
        }

        const float inv0 = 1.f / l0, inv1 = 1.f / l1;
#pragma unroll
        for (int nt = 0; nt < 4; nt++) {
            int col = h * Dd + nt * 8 + cpair;
            uint32_t h0v, l0v, h1v, l1v;
            split2(O[nt][0] * inv0, O[nt][1] * inv0, h0v, l0v);
            split2(O[nt][2] * inv1, O[nt][3] * inv1, h1v, l1v);
            *reinterpret_cast<uint32_t*>(Ah + (rowbase + r0) * GK + col) = h0v;
            *reinterpret_cast<uint32_t*>(Al + (rowbase + r0) * GK + col) = l0v;
            *reinterpret_cast<uint32_t*>(Ah + (rowbase + r1) * GK + col) = h1v;
            *reinterpret_cast<uint32_t*>(Al + (rowbase + r1) * GK + col) = l1v;
        }
        if (e == 0) __syncthreads();
    }
}

extern "C" void kernel_launch(void* const* d_in, const int* in_sizes, int n_in,
                              void* d_out, int out_size) {
    const float* pair      = (const float*)d_in[0];
    const float* bulk      = (const float*)d_in[1];
    const float* row_qkv_w = (const float*)d_in[2];
    const float* row_out_w = (const float*)d_in[3];
    const float* row_ln_g  = (const float*)d_in[4];
    const float* row_ln_b  = (const float*)d_in[5];
    const float* row_bw    = (const float*)d_in[6];
    const float* row_bb    = (const float*)d_in[7];
    const float* col_qkv_w = (const float*)d_in[8];
    const float* col_out_w = (const float*)d_in[9];
    const float* col_ln_g  = (const float*)d_in[10];
    const float* col_ln_b  = (const float*)d_in[11];
    const float* col_bw    = (const float*)d_in[12];
    const float* col_bb    = (const float*)d_in[13];
    float* out = (float*)d_out;

    float *x1, *mapT;
    __nv_bfloat16 *qkvh, *qkvl, *Ah, *Al, *Xh, *Xl, *Brq, *Bro, *Bcq, *Bco;
    cudaGetSymbolAddress((void**)&qkvh, g_qkvh);
    cudaGetSymbolAddress((void**)&qkvl, g_qkvl);
    cudaGetSymbolAddress((void**)&x1,   g_x1);
    cudaGetSymbolAddress((void**)&mapT, g_mapT);
    cudaGetSymbolAddress((void**)&Ah,   g_Ah);
    cudaGetSymbolAddress((void**)&Al,   g_Al);
    cudaGetSymbolAddress((void**)&Xh,   g_Xh);
    cudaGetSymbolAddress((void**)&Xl,   g_Xl);
    cudaGetSymbolAddress((void**)&Brq,  g_Brq);
    cudaGetSymbolAddress((void**)&Bro,  g_Bro);
    cudaGetSymbolAddress((void**)&Bcq,  g_Bcq);
    cudaGetSymbolAddress((void**)&Bco,  g_Bco);

    cudaFuncSetAttribute(attn_mma, cudaFuncAttributeMaxDynamicSharedMemorySize, ATTN_SMEM);
    cudaFuncSetAttribute(gemm_mma, cudaFuncAttributeMaxDynamicSharedMemorySize, GSMEM);
    cudaFuncSetAttribute(gemm_ln,  cudaFuncAttributeMaxDynamicSharedMemorySize, LSMEM);

    const int n4 = ROWS * GK / 4;
    const int gsplitA = (n4 + 255) / 256;
    const int nsplitW = 2 * GK * 768 + 2 * GK * 256;
    dim3 gq(768 / 128, ROWS / 128);
    dim3 ga(Nn, Bb, Hh / 2);
    dim3 gt(Nn / 32, Nn / 32, Bb);

    // ---- prologue ----
    splitW<<<(nsplitW + 255) / 256, 256>>>(row_qkv_w, row_out_w, col_qkv_w, col_out_w,
                                           Brq, Bro, Bcq, Bco);
    tmap_kernel<<<gt, dim3(32, 8)>>>(bulk, mapT);
    splitA<<<gsplitA, 256>>>((const float4*)pair, Ah, Al, n4);

    // ---- pass 1 (row attention) ----
    gemm_mma<<<gq, 256, GSMEM>>>(Ah, Al, Brq, qkvh, qkvl, 768);
    attn_mma<<<ga, 320, ATTN_SMEM>>>(qkvh, qkvl, bulk, row_bw, row_bb, Ah, Al);
    gemm_ln<<<ROWS / 64, 256, LSMEM>>>(Ah, Al, Bro, pair, row_ln_g, row_ln_b, x1, Xh, Xl);

    // ---- pass 2 (column attention) ----
    gemm_mma<<<gq, 256, GSMEM>>>(Xh, Xl, Bcq, qkvh, qkvl, 768);
    attn_mma<<<ga, 320, ATTN_SMEM>>>(qkvh, qkvl, mapT, col_bw, col_bb, Ah, Al);
    gemm_ln<<<ROWS / 64, 256, LSMEM>>>(Ah, Al, Bco, x1, col_ln_g, col_ln_b, out, nullptr, nullptr);
}